// round 1
// baseline (speedup 1.0000x reference)
#include <cuda_runtime.h>
#include <cuda_bf16.h>
#include <math.h>

// Problem dims
#define BB 32
#define SS 2048
#define CC 1536
#define NN 200
#define KSEL 128

// Scratch (no cudaMalloc allowed)
__device__ float g_xsum[BB * CC];
__device__ int   g_maxid[BB];
__device__ float g_score[BB * SS];
__device__ int   g_topk[BB * KSEL];

// ---------------------------------------------------------------------------
// K0: xsum[b,c] = sum_s x[b,s,c]   (HBM-bound, coalesced over c)
// ---------------------------------------------------------------------------
__global__ void xsum_kernel(const float* __restrict__ x) {
    int gid = blockIdx.x * blockDim.x + threadIdx.x;   // 0 .. BB*CC-1
    if (gid >= BB * CC) return;
    int b = gid / CC, c = gid % CC;
    const float* p = x + (size_t)b * SS * CC + c;
    float a0 = 0.f, a1 = 0.f, a2 = 0.f, a3 = 0.f;
    #pragma unroll 4
    for (int s = 0; s < SS; s += 4) {
        a0 += p[(size_t)(s + 0) * CC];
        a1 += p[(size_t)(s + 1) * CC];
        a2 += p[(size_t)(s + 2) * CC];
        a3 += p[(size_t)(s + 3) * CC];
    }
    g_xsum[gid] = (a0 + a1) + (a2 + a3);
}

// ---------------------------------------------------------------------------
// K1: per batch: meanlogit[n] = (xsum[b]/S)·W[n] + bias[n]; argmax -> g_maxid
// One block per b, 256 threads (n < 200 active).
// ---------------------------------------------------------------------------
__global__ void argmax_kernel(const float* __restrict__ W,
                              const float* __restrict__ bias) {
    __shared__ float xs[CC];
    __shared__ float vals[256];
    __shared__ int   idxs[256];
    int b = blockIdx.x;
    for (int c = threadIdx.x; c < CC; c += 256) xs[c] = g_xsum[b * CC + c];
    __syncthreads();

    int n = threadIdx.x;
    float v = -INFINITY;
    if (n < NN) {
        const float* w = W + (size_t)n * CC;
        float acc = 0.f;
        #pragma unroll 8
        for (int c = 0; c < CC; c++) acc = fmaf(xs[c], __ldg(&w[c]), acc);
        v = acc * (1.0f / (float)SS) + __ldg(&bias[n]);
    }
    vals[threadIdx.x] = v;
    idxs[threadIdx.x] = (n < NN) ? n : (1 << 30);
    __syncthreads();
    for (int o = 128; o > 0; o >>= 1) {
        if (threadIdx.x < o) {
            float v2 = vals[threadIdx.x + o];
            int   i2 = idxs[threadIdx.x + o];
            float v1 = vals[threadIdx.x];
            int   i1 = idxs[threadIdx.x];
            if (v2 > v1 || (v2 == v1 && i2 < i1)) {
                vals[threadIdx.x] = v2; idxs[threadIdx.x] = i2;
            }
        }
        __syncthreads();
    }
    if (threadIdx.x == 0) g_maxid[b] = idxs[0];
}

// ---------------------------------------------------------------------------
// K2: main fused GEMM + softmax-score epilogue.
// Per block: 64 tokens x 200 classes, K=1536 in 16-wide chunks.
// Thread layout: tx=tid&15 (class groups, n = tx+16j, j<13), ty=tid>>4
// (token groups, m = ty*4+i). Per-thread 4x13 fp32 accumulators.
// Epilogue: score[token] = logit[id] - max - log(sum exp(logit-max))
//          == log(softmax prob of class id)  (monotone => same ranking)
// ---------------------------------------------------------------------------
#define MTILE 64
__global__ __launch_bounds__(256, 2)
void score_kernel(const float* __restrict__ x,
                  const float* __restrict__ W,
                  const float* __restrict__ bias) {
    __shared__ float x_s[16 * 65];    // [kk][m], pad 65
    __shared__ float w_s[16 * 209];   // [kk][n], pad 209 (odd => conflict-free)

    int tid = threadIdx.x;
    int tx = tid & 15;
    int ty = tid >> 4;
    int token0 = blockIdx.x * MTILE;           // blocks never straddle batches
    int b = token0 >> 11;                      // S = 2048

    float acc[4][13];
    #pragma unroll
    for (int i = 0; i < 4; i++)
        #pragma unroll
        for (int j = 0; j < 13; j++) acc[i][j] = 0.f;

    const float* xbase = x + (size_t)token0 * CC;

    for (int k0 = 0; k0 < CC; k0 += 16) {
        // x tile: 64x16 = 1024 elems, 4/thread, global-coalesced over kk
        #pragma unroll
        for (int r = 0; r < 4; r++) {
            int e = tid + r * 256;
            int m = e >> 4, kk = e & 15;
            x_s[kk * 65 + m] = xbase[(size_t)m * CC + k0 + kk];
        }
        // W tile: 208x16 = 3328 elems, 13/thread, pad rows zeroed
        #pragma unroll
        for (int r = 0; r < 13; r++) {
            int e = tid + r * 256;
            if (e < 3328) {
                int n = e >> 4, kk = e & 15;
                w_s[kk * 209 + n] =
                    (n < NN) ? __ldg(&W[(size_t)n * CC + k0 + kk]) : 0.f;
            }
        }
        __syncthreads();

        #pragma unroll
        for (int kk = 0; kk < 16; kk++) {
            float xv[4];
            #pragma unroll
            for (int i = 0; i < 4; i++) xv[i] = x_s[kk * 65 + ty * 4 + i];
            #pragma unroll
            for (int j = 0; j < 13; j++) {
                float wv = w_s[kk * 209 + tx + 16 * j];
                #pragma unroll
                for (int i = 0; i < 4; i++)
                    acc[i][j] = fmaf(xv[i], wv, acc[i][j]);
            }
        }
        __syncthreads();
    }

    // Epilogue: per token reduce over the 16 tx lanes (within-warp shuffles;
    // lane = (ty&1)*16 + tx, so xor on bits 0..3 stays in the tx group).
    int id = g_maxid[b];
    #pragma unroll
    for (int i = 0; i < 4; i++) {
        float mx = -1e30f;
        #pragma unroll
        for (int j = 0; j < 13; j++) {
            int n = tx + 16 * j;
            if (n < NN) {
                acc[i][j] += __ldg(&bias[n]);
                mx = fmaxf(mx, acc[i][j]);
            }
        }
        #pragma unroll
        for (int o = 8; o > 0; o >>= 1)
            mx = fmaxf(mx, __shfl_xor_sync(0xffffffffu, mx, o));

        float se = 0.f, lv = 0.f;
        #pragma unroll
        for (int j = 0; j < 13; j++) {
            int n = tx + 16 * j;
            if (n < NN) {
                se += expf(acc[i][j] - mx);
                if (n == id) lv = acc[i][j];
            }
        }
        #pragma unroll
        for (int o = 8; o > 0; o >>= 1) {
            se += __shfl_xor_sync(0xffffffffu, se, o);
            lv += __shfl_xor_sync(0xffffffffu, lv, o);
        }
        if (tx == 0)
            g_score[token0 + ty * 4 + i] = lv - mx - logf(se);
    }
}

// ---------------------------------------------------------------------------
// K3: per-batch bitonic sort of 2048 (score desc, index asc), take first 128.
// Matches jax.lax.top_k ordering.
// ---------------------------------------------------------------------------
__global__ void topk_kernel() {
    __shared__ float s[SS];
    __shared__ int   si[SS];
    int b = blockIdx.x;
    for (int t = threadIdx.x; t < SS; t += blockDim.x) {
        s[t]  = g_score[b * SS + t];
        si[t] = t;
    }
    __syncthreads();
    for (int k = 2; k <= SS; k <<= 1) {
        for (int j = k >> 1; j > 0; j >>= 1) {
            for (int t = threadIdx.x; t < SS; t += blockDim.x) {
                int ixj = t ^ j;
                if (ixj > t) {
                    float a = s[t],  c = s[ixj];
                    int  ai = si[t], ci = si[ixj];
                    // "a better than c" under (score desc, idx asc)
                    bool aBetter = (a > c) || (a == c && ai < ci);
                    bool descHere = ((t & k) == 0);
                    bool doSwap = descHere ? !aBetter : aBetter;
                    if (doSwap) {
                        s[t] = c;  s[ixj] = a;
                        si[t] = ci; si[ixj] = ai;
                    }
                }
            }
            __syncthreads();
        }
    }
    for (int t = threadIdx.x; t < KSEL; t += blockDim.x)
        g_topk[b * KSEL + t] = si[t];
}

// ---------------------------------------------------------------------------
// K4: gather out[b, j, :] = x[b, topk[b][j], :]
// ---------------------------------------------------------------------------
__global__ void gather_kernel(const float* __restrict__ x,
                              float* __restrict__ out) {
    int row = blockIdx.x;            // 0 .. BB*KSEL-1
    int b = row >> 7, j = row & (KSEL - 1);
    int sidx = g_topk[b * KSEL + j];
    const float* src = x + ((size_t)b * SS + sidx) * CC;
    float* dst = out + (size_t)row * CC;
    for (int c = threadIdx.x; c < CC; c += blockDim.x) dst[c] = src[c];
}

// ---------------------------------------------------------------------------
extern "C" void kernel_launch(void* const* d_in, const int* in_sizes, int n_in,
                              void* d_out, int out_size) {
    const float* x    = (const float*)d_in[0];   // [32, 2048, 1536]
    const float* W    = (const float*)d_in[1];   // [200, 1536]
    const float* bias = (const float*)d_in[2];   // [200]
    float* out = (float*)d_out;                  // [32, 128, 1536]

    xsum_kernel<<<(BB * CC + 255) / 256, 256>>>(x);
    argmax_kernel<<<BB, 256>>>(W, bias);
    score_kernel<<<(BB * SS) / MTILE, 256>>>(x, W, bias);
    topk_kernel<<<BB, 1024>>>();
    gather_kernel<<<BB * KSEL, 256>>>(x, out);
}

// round 4
// speedup vs baseline: 1.3392x; 1.3392x over previous
#include <cuda_runtime.h>
#include <cuda_bf16.h>
#include <math.h>
#include <stdint.h>

// Problem dims
#define BB 32
#define SS 2048
#define CC 1536
#define NN 200
#define KSEL 128
#define NCAND 256             // candidate pool per batch (2x margin over KSEL)

#define NPAD 224              // class dim padded to 4 warps x 56
#define NCHUNK 96             // K chunks of 16
#define WCH2 (2 * NPAD * 8)   // u32 per chunk of swizzled W, 2 splits (=3584)

// Scratch (no cudaMalloc allowed)
__device__ float g_xsum[BB * CC];
__device__ int   g_maxid[BB];
__device__ float g_score[BB * SS];          // approx scores (stage 1)
__device__ int   g_cand[BB * NCAND];        // candidate token indices
__device__ float g_cscore[BB * NCAND];      // exact scores of candidates
__device__ int   g_topk[BB * KSEL];
__device__ uint32_t g_wswz[NCHUNK * WCH2];  // [chunk][split][n][8 words]

// ---------------------------------------------------------------------------
// bf16 2-way split helpers
// ---------------------------------------------------------------------------
__device__ __forceinline__ void split2(float v, __nv_bfloat16& h,
                                       __nv_bfloat16& l) {
    h = __float2bfloat16(v);
    l = __float2bfloat16(v - __bfloat162float(h));
}
__device__ __forceinline__ uint32_t packbf(__nv_bfloat16 a, __nv_bfloat16 b) {
    unsigned short ua = *reinterpret_cast<unsigned short*>(&a);
    unsigned short ub = *reinterpret_cast<unsigned short*>(&b);
    return (uint32_t)ua | ((uint32_t)ub << 16);
}

// ---------------------------------------------------------------------------
// K-1: W -> 2-way bf16 split, fragment-swizzled in global.
// Word w = (p&3)*2 + (p>>2) holds k-pair p of the 16-wide chunk.
// ---------------------------------------------------------------------------
__global__ void wconv_kernel(const float* __restrict__ W) {
    int i = blockIdx.x * blockDim.x + threadIdx.x;
    if (i >= NCHUNK * NPAD * 8) return;
    int c = i / (NPAD * 8);
    int rem = i % (NPAD * 8);
    int n = rem >> 3, p = rem & 7;
    float v0 = 0.f, v1 = 0.f;
    if (n < NN) {
        int k = c * 16 + 2 * p;
        v0 = W[(size_t)n * CC + k];
        v1 = W[(size_t)n * CC + k + 1];
    }
    __nv_bfloat16 h0, l0, h1, l1;
    split2(v0, h0, l0);
    split2(v1, h1, l1);
    int w = (p & 3) * 2 + (p >> 2);
    int base = c * WCH2 + n * 8 + w;
    g_wswz[base + 0 * NPAD * 8] = packbf(h0, h1);
    g_wswz[base + 1 * NPAD * 8] = packbf(l0, l1);
}

// ---------------------------------------------------------------------------
// K0: xsum[b,c] = sum_s x[b,s,c]
// ---------------------------------------------------------------------------
__global__ void xsum_kernel(const float* __restrict__ x) {
    int gid = blockIdx.x * blockDim.x + threadIdx.x;
    if (gid >= BB * CC) return;
    int b = gid / CC, c = gid % CC;
    const float* p = x + (size_t)b * SS * CC + c;
    float a0 = 0.f, a1 = 0.f, a2 = 0.f, a3 = 0.f;
    #pragma unroll 4
    for (int s = 0; s < SS; s += 4) {
        a0 += p[(size_t)(s + 0) * CC];
        a1 += p[(size_t)(s + 1) * CC];
        a2 += p[(size_t)(s + 2) * CC];
        a3 += p[(size_t)(s + 3) * CC];
    }
    g_xsum[gid] = (a0 + a1) + (a2 + a3);
}

// ---------------------------------------------------------------------------
// K1: per-batch argmax of mean logits (exact fp32, proven round 1).
// ---------------------------------------------------------------------------
__global__ void argmax_kernel(const float* __restrict__ W,
                              const float* __restrict__ bias) {
    __shared__ float xs[CC];
    __shared__ float vals[256];
    __shared__ int   idxs[256];
    int b = blockIdx.x;
    for (int c = threadIdx.x; c < CC; c += 256) xs[c] = g_xsum[b * CC + c];
    __syncthreads();

    int n = threadIdx.x;
    float v = -INFINITY;
    if (n < NN) {
        const float* w = W + (size_t)n * CC;
        float acc = 0.f;
        #pragma unroll 8
        for (int c = 0; c < CC; c++) acc = fmaf(xs[c], __ldg(&w[c]), acc);
        v = acc * (1.0f / (float)SS) + __ldg(&bias[n]);
    }
    vals[threadIdx.x] = v;
    idxs[threadIdx.x] = (n < NN) ? n : (1 << 30);
    __syncthreads();
    for (int o = 128; o > 0; o >>= 1) {
        if (threadIdx.x < o) {
            float v2 = vals[threadIdx.x + o];
            int   i2 = idxs[threadIdx.x + o];
            float v1 = vals[threadIdx.x];
            int   i1 = idxs[threadIdx.x];
            if (v2 > v1 || (v2 == v1 && i2 < i1)) {
                vals[threadIdx.x] = v2; idxs[threadIdx.x] = i2;
            }
        }
        __syncthreads();
    }
    if (threadIdx.x == 0) g_maxid[b] = idxs[0];
}

// ---------------------------------------------------------------------------
// K2: APPROX tensor-core score GEMM (bf16 2-split, 3 terms: hh + lh + hl).
// Only used to pick candidate sets; ~4e-6 noise is fine for a 2x margin.
// Block: 128 tokens x 224 classes; 512 thr = 4(M) x 4(N) warps.
// ---------------------------------------------------------------------------
#define MMA_BF16(d, a, b0_, b1_)                                            \
    asm volatile(                                                           \
        "mma.sync.aligned.m16n8k16.row.col.f32.bf16.bf16.f32 "              \
        "{%0,%1,%2,%3}, {%4,%5,%6,%7}, {%8,%9}, {%0,%1,%2,%3};"             \
        : "+f"(d[0]), "+f"(d[1]), "+f"(d[2]), "+f"(d[3])                    \
        : "r"(a[0]), "r"(a[1]), "r"(a[2]), "r"(a[3]), "r"(b0_), "r"(b1_))

#define XS2 (2 * 128 * 8)   // u32 per x buffer stage (2 splits)
#define SMEM_BYTES ((2 * XS2 + 2 * WCH2 + NPAD + 3 * 512) * 4)

__global__ __launch_bounds__(512, 1)
void score_mma_kernel(const float* __restrict__ x,
                      const float* __restrict__ bias) {
    extern __shared__ unsigned char sm_raw[];
    uint32_t* xs = (uint32_t*)sm_raw;                 // [2][2][128][8]
    uint32_t* ws = xs + 2 * XS2;                      // [2][2][224][8]
    float* bias_s = (float*)(ws + 2 * WCH2);          // [224]
    float* p_mx = bias_s + NPAD;                      // [128][4]
    float* p_se = p_mx + 512;
    float* p_lv = p_se + 512;

    int tid  = threadIdx.x;
    int warp = tid >> 5, lane = tid & 31;
    int gid  = lane >> 2, tig = lane & 3;
    int mw   = warp >> 2, nw = warp & 3;
    int token0 = blockIdx.x * 128;        // 16 blocks per batch
    int b = token0 >> 11;

    for (int n = tid; n < NPAD; n += 512)
        bias_s[n] = (n < NN) ? __ldg(&bias[n]) : -1e30f;

    float acc[2][7][4];
    #pragma unroll
    for (int mt = 0; mt < 2; mt++)
        #pragma unroll
        for (int nt = 0; nt < 7; nt++)
            #pragma unroll
            for (int r = 0; r < 4; r++) acc[mt][nt][r] = 0.f;

    const float* xbase = x + (size_t)token0 * CC;

    float2 rx[2];
    uint4  rw[2];
    int xrow[2], xp[2];
    #pragma unroll
    for (int t = 0; t < 2; t++) {
        int task = tid + t * 512;
        xrow[t] = task >> 3;
        xp[t]   = task & 7;
    }

    auto load_regs = [&](int c) {
        #pragma unroll
        for (int t = 0; t < 2; t++)
            rx[t] = *(const float2*)&xbase[(size_t)xrow[t] * CC + c * 16 + 2 * xp[t]];
        const uint4* wsrc = (const uint4*)(g_wswz + (size_t)c * WCH2);
        #pragma unroll
        for (int r = 0; r < 2; r++) {
            int e = tid + r * 512;
            if (e < WCH2 / 4) rw[r] = __ldg(&wsrc[e]);
        }
    };
    auto store_smem = [&](int buf) {
        #pragma unroll
        for (int t = 0; t < 2; t++) {
            __nv_bfloat16 h0, l0, h1, l1;
            split2(rx[t].x, h0, l0);
            split2(rx[t].y, h1, l1);
            int w = (xp[t] & 3) * 2 + (xp[t] >> 2);
            int base = buf * XS2 + xrow[t] * 8 + w;
            xs[base + 0 * 128 * 8] = packbf(h0, h1);
            xs[base + 1 * 128 * 8] = packbf(l0, l1);
        }
        uint4* wdst = (uint4*)(ws + buf * WCH2);
        #pragma unroll
        for (int r = 0; r < 2; r++) {
            int e = tid + r * 512;
            if (e < WCH2 / 4) wdst[e] = rw[r];
        }
    };

    load_regs(0);
    store_smem(0);
    __syncthreads();

    for (int c = 0; c < NCHUNK; c++) {
        int buf = c & 1;
        if (c + 1 < NCHUNK) load_regs(c + 1);

        // A fragments: [mt][split][4]
        uint32_t af[2][2][4];
        #pragma unroll
        for (int mt = 0; mt < 2; mt++) {
            int row0 = mw * 32 + mt * 16 + gid;
            #pragma unroll
            for (int s = 0; s < 2; s++) {
                const uint32_t* pa =
                    xs + (buf * 2 + s) * 128 * 8 + row0 * 8 + tig * 2;
                uint2 t0 = *(const uint2*)pa;               // row gid
                uint2 t1 = *(const uint2*)(pa + 64);        // row gid+8
                af[mt][s][0] = t0.x;  af[mt][s][2] = t0.y;
                af[mt][s][1] = t1.x;  af[mt][s][3] = t1.y;
            }
        }

        #pragma unroll
        for (int nt = 0; nt < 7; nt++) {
            int nrow = nw * 56 + nt * 8 + gid;
            const uint32_t* pb = ws + buf * WCH2 + nrow * 8 + tig * 2;
            uint2 B0 = *(const uint2*)pb;                   // W hi
            uint2 B1 = *(const uint2*)(pb + NPAD * 8);      // W lo
            #pragma unroll
            for (int mt = 0; mt < 2; mt++) {
                MMA_BF16(acc[mt][nt], af[mt][0], B0.x, B0.y);   // hh
                MMA_BF16(acc[mt][nt], af[mt][1], B0.x, B0.y);   // lh
                MMA_BF16(acc[mt][nt], af[mt][0], B1.x, B1.y);   // hl
            }
        }

        if (c + 1 < NCHUNK) store_smem(buf ^ 1);
        __syncthreads();
    }

    // ---- Epilogue: bias, per-token log-softmax score of class g_maxid[b]
    int id = g_maxid[b];
    #pragma unroll
    for (int nt = 0; nt < 7; nt++) {
        int n0 = nw * 56 + nt * 8 + tig * 2;
        float b0 = bias_s[n0], b1 = bias_s[n0 + 1];
        #pragma unroll
        for (int mt = 0; mt < 2; mt++) {
            acc[mt][nt][0] += b0; acc[mt][nt][1] += b1;
            acc[mt][nt][2] += b0; acc[mt][nt][3] += b1;
        }
    }

    #pragma unroll
    for (int mt = 0; mt < 2; mt++) {
        #pragma unroll
        for (int half = 0; half < 2; half++) {
            float mx = -1e30f;
            #pragma unroll
            for (int nt = 0; nt < 7; nt++)
                mx = fmaxf(mx, fmaxf(acc[mt][nt][2 * half],
                                     acc[mt][nt][2 * half + 1]));
            mx = fmaxf(mx, __shfl_xor_sync(0xffffffffu, mx, 1));
            mx = fmaxf(mx, __shfl_xor_sync(0xffffffffu, mx, 2));

            float se = 0.f, lv = 0.f;
            #pragma unroll
            for (int nt = 0; nt < 7; nt++) {
                int n0 = nw * 56 + nt * 8 + tig * 2;
                float v0 = acc[mt][nt][2 * half];
                float v1 = acc[mt][nt][2 * half + 1];
                se += expf(v0 - mx) + expf(v1 - mx);
                if (n0 == id)     lv = v0;
                if (n0 + 1 == id) lv = v1;
            }
            se += __shfl_xor_sync(0xffffffffu, se, 1);
            se += __shfl_xor_sync(0xffffffffu, se, 2);
            lv += __shfl_xor_sync(0xffffffffu, lv, 1);
            lv += __shfl_xor_sync(0xffffffffu, lv, 2);

            if (tig == 0) {
                int row = mw * 32 + mt * 16 + half * 8 + gid;
                p_mx[row * 4 + nw] = mx;
                p_se[row * 4 + nw] = se;
                p_lv[row * 4 + nw] = lv;
            }
        }
    }
    __syncthreads();

    if (tid < 128) {
        float m0 = p_mx[tid * 4 + 0], m1 = p_mx[tid * 4 + 1];
        float m2 = p_mx[tid * 4 + 2], m3 = p_mx[tid * 4 + 3];
        float M = fmaxf(fmaxf(m0, m1), fmaxf(m2, m3));
        float se = p_se[tid * 4 + 0] * expf(m0 - M)
                 + p_se[tid * 4 + 1] * expf(m1 - M)
                 + p_se[tid * 4 + 2] * expf(m2 - M)
                 + p_se[tid * 4 + 3] * expf(m3 - M);
        float lv = p_lv[tid * 4 + 0] + p_lv[tid * 4 + 1]
                 + p_lv[tid * 4 + 2] + p_lv[tid * 4 + 3];
        g_score[token0 + tid] = lv - M - logf(se);
    }
}

// ---------------------------------------------------------------------------
// K3: per-batch bitonic sort of 2048 approx scores -> top-256 candidates.
// ---------------------------------------------------------------------------
__global__ void cand_kernel() {
    __shared__ float s[SS];
    __shared__ int   si[SS];
    int b = blockIdx.x;
    for (int t = threadIdx.x; t < SS; t += blockDim.x) {
        s[t]  = g_score[b * SS + t];
        si[t] = t;
    }
    __syncthreads();
    for (int k = 2; k <= SS; k <<= 1) {
        for (int j = k >> 1; j > 0; j >>= 1) {
            for (int t = threadIdx.x; t < SS; t += blockDim.x) {
                int ixj = t ^ j;
                if (ixj > t) {
                    float a = s[t],  c = s[ixj];
                    int  ai = si[t], ci = si[ixj];
                    bool aBetter = (a > c) || (a == c && ai < ci);
                    bool descHere = ((t & k) == 0);
                    bool doSwap = descHere ? !aBetter : aBetter;
                    if (doSwap) {
                        s[t] = c;  s[ixj] = a;
                        si[t] = ci; si[ixj] = ai;
                    }
                }
            }
            __syncthreads();
        }
    }
    for (int t = threadIdx.x; t < NCAND; t += blockDim.x)
        g_cand[b * NCAND + t] = si[t];
}

// ---------------------------------------------------------------------------
// K4: EXACT rescore of candidates — verbatim round-1 fp32 math (proven
// rel_err 0.0). Block: 64 candidates x 200 classes; grid BB*NCAND/64 = 128.
// ---------------------------------------------------------------------------
__global__ __launch_bounds__(256, 2)
void exact_kernel(const float* __restrict__ x,
                  const float* __restrict__ W,
                  const float* __restrict__ bias) {
    __shared__ float x_s[16 * 65];
    __shared__ float w_s[16 * 209];
    __shared__ int   cind[64];

    int tid = threadIdx.x;
    int tx = tid & 15;
    int ty = tid >> 4;
    int b  = blockIdx.x >> 2;              // 4 blocks per batch
    int c0 = (blockIdx.x & 3) * 64;        // candidate offset within batch

    if (tid < 64) cind[tid] = g_cand[b * NCAND + c0 + tid];
    __syncthreads();

    float acc[4][13];
    #pragma unroll
    for (int i = 0; i < 4; i++)
        #pragma unroll
        for (int j = 0; j < 13; j++) acc[i][j] = 0.f;

    const float* xb = x + (size_t)b * SS * CC;

    for (int k0 = 0; k0 < CC; k0 += 16) {
        #pragma unroll
        for (int r = 0; r < 4; r++) {
            int e = tid + r * 256;
            int m = e >> 4, kk = e & 15;
            x_s[kk * 65 + m] = xb[(size_t)cind[m] * CC + k0 + kk];
        }
        #pragma unroll
        for (int r = 0; r < 13; r++) {
            int e = tid + r * 256;
            if (e < 3328) {
                int n = e >> 4, kk = e & 15;
                w_s[kk * 209 + n] =
                    (n < NN) ? __ldg(&W[(size_t)n * CC + k0 + kk]) : 0.f;
            }
        }
        __syncthreads();

        #pragma unroll
        for (int kk = 0; kk < 16; kk++) {
            float xv[4];
            #pragma unroll
            for (int i = 0; i < 4; i++) xv[i] = x_s[kk * 65 + ty * 4 + i];
            #pragma unroll
            for (int j = 0; j < 13; j++) {
                float wv = w_s[kk * 209 + tx + 16 * j];
                #pragma unroll
                for (int i = 0; i < 4; i++)
                    acc[i][j] = fmaf(xv[i], wv, acc[i][j]);
            }
        }
        __syncthreads();
    }

    int id = g_maxid[b];
    #pragma unroll
    for (int i = 0; i < 4; i++) {
        float mx = -1e30f;
        #pragma unroll
        for (int j = 0; j < 13; j++) {
            int n = tx + 16 * j;
            if (n < NN) {
                acc[i][j] += __ldg(&bias[n]);
                mx = fmaxf(mx, acc[i][j]);
            }
        }
        #pragma unroll
        for (int o = 8; o > 0; o >>= 1)
            mx = fmaxf(mx, __shfl_xor_sync(0xffffffffu, mx, o));

        float se = 0.f, lv = 0.f;
        #pragma unroll
        for (int j = 0; j < 13; j++) {
            int n = tx + 16 * j;
            if (n < NN) {
                se += expf(acc[i][j] - mx);
                if (n == id) lv = acc[i][j];
            }
        }
        #pragma unroll
        for (int o = 8; o > 0; o >>= 1) {
            se += __shfl_xor_sync(0xffffffffu, se, o);
            lv += __shfl_xor_sync(0xffffffffu, lv, o);
        }
        if (tx == 0)
            g_cscore[b * NCAND + c0 + ty * 4 + i] = lv - mx - logf(se);
    }
}

// ---------------------------------------------------------------------------
// K5: per-batch sort of 256 candidates by EXACT score (desc, token idx asc);
// emit top-128 token indices.
// ---------------------------------------------------------------------------
__global__ void sort2_kernel() {
    __shared__ float s[NCAND];
    __shared__ int   si[NCAND];
    int b = blockIdx.x;
    int t = threadIdx.x;                   // 256 threads, 1 elem each
    s[t]  = g_cscore[b * NCAND + t];
    si[t] = g_cand[b * NCAND + t];
    __syncthreads();
    for (int k = 2; k <= NCAND; k <<= 1) {
        for (int j = k >> 1; j > 0; j >>= 1) {
            int ixj = t ^ j;
            if (ixj > t) {
                float a = s[t],  c = s[ixj];
                int  ai = si[t], ci = si[ixj];
                bool aBetter = (a > c) || (a == c && ai < ci);
                bool descHere = ((t & k) == 0);
                bool doSwap = descHere ? !aBetter : aBetter;
                if (doSwap) {
                    s[t] = c;  s[ixj] = a;
                    si[t] = ci; si[ixj] = ai;
                }
            }
            __syncthreads();
        }
    }
    if (t < KSEL) g_topk[b * KSEL + t] = si[t];
}

// ---------------------------------------------------------------------------
// K6: gather out[b, j, :] = x[b, topk[b][j], :]
// ---------------------------------------------------------------------------
__global__ void gather_kernel(const float* __restrict__ x,
                              float* __restrict__ out) {
    int row = blockIdx.x;
    int b = row >> 7, j = row & (KSEL - 1);
    int sidx = g_topk[b * KSEL + j];
    const float* src = x + ((size_t)b * SS + sidx) * CC;
    float* dst = out + (size_t)row * CC;
    for (int c = threadIdx.x; c < CC; c += blockDim.x) dst[c] = src[c];
}

// ---------------------------------------------------------------------------
extern "C" void kernel_launch(void* const* d_in, const int* in_sizes, int n_in,
                              void* d_out, int out_size) {
    const float* x    = (const float*)d_in[0];   // [32, 2048, 1536]
    const float* W    = (const float*)d_in[1];   // [200, 1536]
    const float* bias = (const float*)d_in[2];   // [200]
    float* out = (float*)d_out;                  // [32, 128, 1536]

    cudaFuncSetAttribute(score_mma_kernel,
                         cudaFuncAttributeMaxDynamicSharedMemorySize,
                         SMEM_BYTES);

    wconv_kernel<<<(NCHUNK * NPAD * 8 + 255) / 256, 256>>>(W);
    xsum_kernel<<<(BB * CC + 255) / 256, 256>>>(x);
    argmax_kernel<<<BB, 256>>>(W, bias);
    score_mma_kernel<<<(BB * SS) / 128, 512, SMEM_BYTES>>>(x, bias);
    cand_kernel<<<BB, 1024>>>();
    exact_kernel<<<(BB * NCAND) / 64, 256>>>(x, W, bias);
    sort2_kernel<<<BB, NCAND>>>();
    gather_kernel<<<BB * KSEL, 256>>>(x, out);
}

// round 5
// speedup vs baseline: 2.0938x; 1.5635x over previous
#include <cuda_runtime.h>
#include <cuda_bf16.h>
#include <math.h>
#include <stdint.h>

// Problem dims
#define BB 32
#define SS 2048
#define CC 1536
#define NN 200
#define KSEL 128
#define NCAND 256             // candidate pool per batch (2x margin over KSEL)
#define TOT (BB * SS)         // 65536 tokens

#define NPAD 224              // class dim padded to 4 warps x 56
#define NCHUNK 96             // K chunks of 16
#define WCH1 (NPAD * 8)       // u32 per chunk of swizzled W (single bf16) =1792

// Scratch (no cudaMalloc allowed)
__device__ float g_logits[(size_t)NN * TOT];   // [n][token], 52.4 MB
__device__ float g_lse[TOT];                   // per-token logsumexp
__device__ float g_msum[BB * NN];              // per-(b,n) logit sums
__device__ int   g_maxid[BB];
__device__ float g_score[TOT];                 // approx scores (stage 1)
__device__ int   g_cand[BB * NCAND];           // candidate token indices
__device__ float g_cscore[BB * NCAND];         // exact scores of candidates
__device__ int   g_topk[BB * KSEL];
__device__ uint32_t g_wswz[NCHUNK * WCH1];     // [chunk][n][8 words]

__device__ __forceinline__ uint32_t pack2bf(float a, float b) {
    __nv_bfloat162 p = __float22bfloat162_rn(make_float2(a, b));
    return *reinterpret_cast<uint32_t*>(&p);
}

// ---------------------------------------------------------------------------
// K-1: W -> bf16, fragment-swizzled in global.
// Word w = (p&3)*2 + (p>>2) holds k-pair p of the 16-wide chunk.
// ---------------------------------------------------------------------------
__global__ void wconv_kernel(const float* __restrict__ W) {
    int i = blockIdx.x * blockDim.x + threadIdx.x;
    if (i >= NCHUNK * WCH1) return;
    int c = i / WCH1;
    int rem = i % WCH1;
    int n = rem >> 3, p = rem & 7;
    float v0 = 0.f, v1 = 0.f;
    if (n < NN) {
        int k = c * 16 + 2 * p;
        v0 = W[(size_t)n * CC + k];
        v1 = W[(size_t)n * CC + k + 1];
    }
    int w = (p & 3) * 2 + (p >> 2);
    g_wswz[c * WCH1 + n * 8 + w] = pack2bf(v0, v1);
}

// ---------------------------------------------------------------------------
// K2: APPROX tensor-core logits GEMM (pure bf16, 1 MMA term).
// Block: 128 tokens x 224 classes; 512 thr = 4(M) x 4(N) warps.
// Stores: g_logits[n][token] (fp32, bias included) and g_lse[token].
// ---------------------------------------------------------------------------
#define MMA_BF16(d, a, b0_, b1_)                                            \
    asm volatile(                                                           \
        "mma.sync.aligned.m16n8k16.row.col.f32.bf16.bf16.f32 "              \
        "{%0,%1,%2,%3}, {%4,%5,%6,%7}, {%8,%9}, {%0,%1,%2,%3};"             \
        : "+f"(d[0]), "+f"(d[1]), "+f"(d[2]), "+f"(d[3])                    \
        : "r"(a[0]), "r"(a[1]), "r"(a[2]), "r"(a[3]), "r"(b0_), "r"(b1_))

#define XS1 (128 * 8)   // u32 per x buffer stage

__global__ __launch_bounds__(512, 1)
void score_mma_kernel(const float* __restrict__ x,
                      const float* __restrict__ bias) {
    __shared__ uint32_t xs[2 * XS1];        // [2][128][8]
    __shared__ uint32_t ws[2 * WCH1];       // [2][224][8]
    __shared__ float bias_s[NPAD];
    __shared__ float p_mx[128 * 4], p_se[128 * 4];

    int tid  = threadIdx.x;
    int warp = tid >> 5, lane = tid & 31;
    int gid  = lane >> 2, tig = lane & 3;
    int mw   = warp >> 2, nw = warp & 3;
    int token0 = blockIdx.x * 128;        // 16 blocks per batch

    for (int n = tid; n < NPAD; n += 512)
        bias_s[n] = (n < NN) ? __ldg(&bias[n]) : -1e30f;

    float acc[2][7][4];
    #pragma unroll
    for (int mt = 0; mt < 2; mt++)
        #pragma unroll
        for (int nt = 0; nt < 7; nt++)
            #pragma unroll
            for (int r = 0; r < 4; r++) acc[mt][nt][r] = 0.f;

    const float* xbase = x + (size_t)token0 * CC;

    float2 rx[2];
    uint4  rw;
    int xrow[2], xp[2];
    #pragma unroll
    for (int t = 0; t < 2; t++) {
        int task = tid + t * 512;
        xrow[t] = task >> 3;
        xp[t]   = task & 7;
    }

    auto load_regs = [&](int c) {
        #pragma unroll
        for (int t = 0; t < 2; t++)
            rx[t] = *(const float2*)&xbase[(size_t)xrow[t] * CC + c * 16 + 2 * xp[t]];
        const uint4* wsrc = (const uint4*)(g_wswz + (size_t)c * WCH1);
        if (tid < WCH1 / 4) rw = __ldg(&wsrc[tid]);
    };
    auto store_smem = [&](int buf) {
        #pragma unroll
        for (int t = 0; t < 2; t++) {
            int w = (xp[t] & 3) * 2 + (xp[t] >> 2);
            xs[buf * XS1 + xrow[t] * 8 + w] = pack2bf(rx[t].x, rx[t].y);
        }
        uint4* wdst = (uint4*)(ws + buf * WCH1);
        if (tid < WCH1 / 4) wdst[tid] = rw;
    };

    load_regs(0);
    store_smem(0);
    __syncthreads();

    for (int c = 0; c < NCHUNK; c++) {
        int buf = c & 1;
        if (c + 1 < NCHUNK) load_regs(c + 1);

        uint32_t af[2][4];
        #pragma unroll
        for (int mt = 0; mt < 2; mt++) {
            int row0 = mw * 32 + mt * 16 + gid;
            const uint32_t* pa = xs + buf * XS1 + row0 * 8 + tig * 2;
            uint2 t0 = *(const uint2*)pa;               // row gid
            uint2 t1 = *(const uint2*)(pa + 64);        // row gid+8
            af[mt][0] = t0.x;  af[mt][2] = t0.y;
            af[mt][1] = t1.x;  af[mt][3] = t1.y;
        }

        #pragma unroll
        for (int nt = 0; nt < 7; nt++) {
            int nrow = nw * 56 + nt * 8 + gid;
            uint2 B0 = *(const uint2*)(ws + buf * WCH1 + nrow * 8 + tig * 2);
            MMA_BF16(acc[0][nt], af[0], B0.x, B0.y);
            MMA_BF16(acc[1][nt], af[1], B0.x, B0.y);
        }

        if (c + 1 < NCHUNK) store_smem(buf ^ 1);
        __syncthreads();
    }

    // ---- bias add + logit store (transposed [n][token]) + LSE
    #pragma unroll
    for (int nt = 0; nt < 7; nt++) {
        int n0 = nw * 56 + nt * 8 + tig * 2;
        float b0 = bias_s[n0], b1 = bias_s[n0 + 1];
        #pragma unroll
        for (int mt = 0; mt < 2; mt++) {
            acc[mt][nt][0] += b0; acc[mt][nt][1] += b1;
            acc[mt][nt][2] += b0; acc[mt][nt][3] += b1;
        }
        if (n0 < NN) {
            #pragma unroll
            for (int mt = 0; mt < 2; mt++) {
                int r0 = token0 + mw * 32 + mt * 16 + gid;
                g_logits[(size_t)n0 * TOT + r0]           = acc[mt][nt][0];
                g_logits[(size_t)(n0 + 1) * TOT + r0]     = acc[mt][nt][1];
                g_logits[(size_t)n0 * TOT + r0 + 8]       = acc[mt][nt][2];
                g_logits[(size_t)(n0 + 1) * TOT + r0 + 8] = acc[mt][nt][3];
            }
        }
    }

    #pragma unroll
    for (int mt = 0; mt < 2; mt++) {
        #pragma unroll
        for (int half = 0; half < 2; half++) {
            float mx = -1e30f;
            #pragma unroll
            for (int nt = 0; nt < 7; nt++)
                mx = fmaxf(mx, fmaxf(acc[mt][nt][2 * half],
                                     acc[mt][nt][2 * half + 1]));
            mx = fmaxf(mx, __shfl_xor_sync(0xffffffffu, mx, 1));
            mx = fmaxf(mx, __shfl_xor_sync(0xffffffffu, mx, 2));

            float se = 0.f;
            #pragma unroll
            for (int nt = 0; nt < 7; nt++) {
                se += expf(acc[mt][nt][2 * half] - mx)
                    + expf(acc[mt][nt][2 * half + 1] - mx);
            }
            se += __shfl_xor_sync(0xffffffffu, se, 1);
            se += __shfl_xor_sync(0xffffffffu, se, 2);

            if (tig == 0) {
                int row = mw * 32 + mt * 16 + half * 8 + gid;
                p_mx[row * 4 + nw] = mx;
                p_se[row * 4 + nw] = se;
            }
        }
    }
    __syncthreads();

    if (tid < 128) {
        float m0 = p_mx[tid * 4 + 0], m1 = p_mx[tid * 4 + 1];
        float m2 = p_mx[tid * 4 + 2], m3 = p_mx[tid * 4 + 3];
        float M = fmaxf(fmaxf(m0, m1), fmaxf(m2, m3));
        float se = p_se[tid * 4 + 0] * expf(m0 - M)
                 + p_se[tid * 4 + 1] * expf(m1 - M)
                 + p_se[tid * 4 + 2] * expf(m2 - M)
                 + p_se[tid * 4 + 3] * expf(m3 - M);
        g_lse[token0 + tid] = M + logf(se);
    }
}

// ---------------------------------------------------------------------------
// K3a: per-(b,n) sum of logits over tokens (bias included — constant shift).
// ---------------------------------------------------------------------------
__global__ void csum_kernel() {
    __shared__ float red[128];
    int b = blockIdx.x / NN, n = blockIdx.x % NN;
    const float* p = g_logits + (size_t)n * TOT + b * SS;
    float s = 0.f;
    for (int t = threadIdx.x; t < SS; t += 128) s += p[t];
    red[threadIdx.x] = s;
    __syncthreads();
    for (int o = 64; o > 0; o >>= 1) {
        if (threadIdx.x < o) red[threadIdx.x] += red[threadIdx.x + o];
        __syncthreads();
    }
    if (threadIdx.x == 0) g_msum[b * NN + n] = red[0];
}

// ---------------------------------------------------------------------------
// K3b: per-batch argmax over the NN sums.
// ---------------------------------------------------------------------------
__global__ void argmax2_kernel() {
    __shared__ float vals[256];
    __shared__ int   idxs[256];
    int b = blockIdx.x, n = threadIdx.x;
    vals[n] = (n < NN) ? g_msum[b * NN + n] : -INFINITY;
    idxs[n] = (n < NN) ? n : (1 << 30);
    __syncthreads();
    for (int o = 128; o > 0; o >>= 1) {
        if (n < o) {
            float v2 = vals[n + o]; int i2 = idxs[n + o];
            float v1 = vals[n];     int i1 = idxs[n];
            if (v2 > v1 || (v2 == v1 && i2 < i1)) { vals[n] = v2; idxs[n] = i2; }
        }
        __syncthreads();
    }
    if (n == 0) g_maxid[b] = idxs[0];
}

// ---------------------------------------------------------------------------
// K3c: per-token approx score = logit[id] - lse.
// ---------------------------------------------------------------------------
__global__ void fill_kernel() {
    int t = blockIdx.x * blockDim.x + threadIdx.x;
    if (t >= TOT) return;
    int b = t >> 11;
    int id = g_maxid[b];
    g_score[t] = g_logits[(size_t)id * TOT + t] - g_lse[t];
}

// ---------------------------------------------------------------------------
// K4: per-batch bitonic sort of 2048 approx scores -> top-256 candidates.
// ---------------------------------------------------------------------------
__global__ void cand_kernel() {
    __shared__ float s[SS];
    __shared__ int   si[SS];
    int b = blockIdx.x;
    for (int t = threadIdx.x; t < SS; t += blockDim.x) {
        s[t]  = g_score[b * SS + t];
        si[t] = t;
    }
    __syncthreads();
    for (int k = 2; k <= SS; k <<= 1) {
        for (int j = k >> 1; j > 0; j >>= 1) {
            for (int t = threadIdx.x; t < SS; t += blockDim.x) {
                int ixj = t ^ j;
                if (ixj > t) {
                    float a = s[t],  c = s[ixj];
                    int  ai = si[t], ci = si[ixj];
                    bool aBetter = (a > c) || (a == c && ai < ci);
                    bool descHere = ((t & k) == 0);
                    bool doSwap = descHere ? !aBetter : aBetter;
                    if (doSwap) {
                        s[t] = c;  s[ixj] = a;
                        si[t] = ci; si[ixj] = ai;
                    }
                }
            }
            __syncthreads();
        }
    }
    for (int t = threadIdx.x; t < NCAND; t += blockDim.x)
        g_cand[b * NCAND + t] = si[t];
}

// ---------------------------------------------------------------------------
// K5: EXACT rescore of candidates — verbatim round-1 fp32 math (proven
// rel_err 0.0). Block: 64 candidates x 200 classes; grid 128.
// ---------------------------------------------------------------------------
__global__ __launch_bounds__(256, 2)
void exact_kernel(const float* __restrict__ x,
                  const float* __restrict__ W,
                  const float* __restrict__ bias) {
    __shared__ float x_s[16 * 65];
    __shared__ float w_s[16 * 209];
    __shared__ int   cind[64];

    int tid = threadIdx.x;
    int tx = tid & 15;
    int ty = tid >> 4;
    int b  = blockIdx.x >> 2;              // 4 blocks per batch
    int c0 = (blockIdx.x & 3) * 64;

    if (tid < 64) cind[tid] = g_cand[b * NCAND + c0 + tid];
    __syncthreads();

    float acc[4][13];
    #pragma unroll
    for (int i = 0; i < 4; i++)
        #pragma unroll
        for (int j = 0; j < 13; j++) acc[i][j] = 0.f;

    const float* xb = x + (size_t)b * SS * CC;

    for (int k0 = 0; k0 < CC; k0 += 16) {
        #pragma unroll
        for (int r = 0; r < 4; r++) {
            int e = tid + r * 256;
            int m = e >> 4, kk = e & 15;
            x_s[kk * 65 + m] = xb[(size_t)cind[m] * CC + k0 + kk];
        }
        #pragma unroll
        for (int r = 0; r < 13; r++) {
            int e = tid + r * 256;
            if (e < 3328) {
                int n = e >> 4, kk = e & 15;
                w_s[kk * 209 + n] =
                    (n < NN) ? __ldg(&W[(size_t)n * CC + k0 + kk]) : 0.f;
            }
        }
        __syncthreads();

        #pragma unroll
        for (int kk = 0; kk < 16; kk++) {
            float xv[4];
            #pragma unroll
            for (int i = 0; i < 4; i++) xv[i] = x_s[kk * 65 + ty * 4 + i];
            #pragma unroll
            for (int j = 0; j < 13; j++) {
                float wv = w_s[kk * 209 + tx + 16 * j];
                #pragma unroll
                for (int i = 0; i < 4; i++)
                    acc[i][j] = fmaf(xv[i], wv, acc[i][j]);
            }
        }
        __syncthreads();
    }

    int id = g_maxid[b];
    #pragma unroll
    for (int i = 0; i < 4; i++) {
        float mx = -1e30f;
        #pragma unroll
        for (int j = 0; j < 13; j++) {
            int n = tx + 16 * j;
            if (n < NN) {
                acc[i][j] += __ldg(&bias[n]);
                mx = fmaxf(mx, acc[i][j]);
            }
        }
        #pragma unroll
        for (int o = 8; o > 0; o >>= 1)
            mx = fmaxf(mx, __shfl_xor_sync(0xffffffffu, mx, o));

        float se = 0.f, lv = 0.f;
        #pragma unroll
        for (int j = 0; j < 13; j++) {
            int n = tx + 16 * j;
            if (n < NN) {
                se += expf(acc[i][j] - mx);
                if (n == id) lv = acc[i][j];
            }
        }
        #pragma unroll
        for (int o = 8; o > 0; o >>= 1) {
            se += __shfl_xor_sync(0xffffffffu, se, o);
            lv += __shfl_xor_sync(0xffffffffu, lv, o);
        }
        if (tx == 0)
            g_cscore[b * NCAND + c0 + ty * 4 + i] = lv - mx - logf(se);
    }
}

// ---------------------------------------------------------------------------
// K6: per-batch sort of 256 candidates by EXACT score (desc, idx asc).
// ---------------------------------------------------------------------------
__global__ void sort2_kernel() {
    __shared__ float s[NCAND];
    __shared__ int   si[NCAND];
    int b = blockIdx.x;
    int t = threadIdx.x;
    s[t]  = g_cscore[b * NCAND + t];
    si[t] = g_cand[b * NCAND + t];
    __syncthreads();
    for (int k = 2; k <= NCAND; k <<= 1) {
        for (int j = k >> 1; j > 0; j >>= 1) {
            int ixj = t ^ j;
            if (ixj > t) {
                float a = s[t],  c = s[ixj];
                int  ai = si[t], ci = si[ixj];
                bool aBetter = (a > c) || (a == c && ai < ci);
                bool descHere = ((t & k) == 0);
                bool doSwap = descHere ? !aBetter : aBetter;
                if (doSwap) {
                    s[t] = c;  s[ixj] = a;
                    si[t] = ci; si[ixj] = ai;
                }
            }
            __syncthreads();
        }
    }
    if (t < KSEL) g_topk[b * KSEL + t] = si[t];
}

// ---------------------------------------------------------------------------
// K7: gather out[b, j, :] = x[b, topk[b][j], :]
// ---------------------------------------------------------------------------
__global__ void gather_kernel(const float* __restrict__ x,
                              float* __restrict__ out) {
    int row = blockIdx.x;
    int b = row >> 7, j = row & (KSEL - 1);
    int sidx = g_topk[b * KSEL + j];
    const float* src = x + ((size_t)b * SS + sidx) * CC;
    float* dst = out + (size_t)row * CC;
    for (int c = threadIdx.x; c < CC; c += blockDim.x) dst[c] = src[c];
}

// ---------------------------------------------------------------------------
extern "C" void kernel_launch(void* const* d_in, const int* in_sizes, int n_in,
                              void* d_out, int out_size) {
    const float* x    = (const float*)d_in[0];   // [32, 2048, 1536]
    const float* W    = (const float*)d_in[1];   // [200, 1536]
    const float* bias = (const float*)d_in[2];   // [200]
    float* out = (float*)d_out;                  // [32, 128, 1536]

    wconv_kernel<<<(NCHUNK * WCH1 + 255) / 256, 256>>>(W);
    score_mma_kernel<<<TOT / 128, 512>>>(x, bias);
    csum_kernel<<<BB * NN, 128>>>();
    argmax2_kernel<<<BB, 256>>>();
    fill_kernel<<<(TOT + 255) / 256, 256>>>();
    cand_kernel<<<BB, 1024>>>();
    exact_kernel<<<(BB * NCAND) / 64, 256>>>(x, W, bias);
    sort2_kernel<<<BB, NCAND>>>();
    gather_kernel<<<BB * KSEL, 256>>>(x, out);
}

// round 6
// speedup vs baseline: 2.4896x; 1.1890x over previous
#include <cuda_runtime.h>
#include <cuda_bf16.h>
#include <math.h>
#include <stdint.h>

// Problem dims
#define BB 32
#define SS 2048
#define CC 1536
#define NN 200
#define KSEL 128
#define NCAND 256
#define TOT (BB * SS)         // 65536 tokens

#define NPAD 224              // class dim padded to 4 warps x 56
#define NCH16 96              // K chunks of 16
#define NCH32 48              // K chunks of 32
#define WCH1 (NPAD * 8)       // u32 per k16 chunk of swizzled W = 1792

// Scratch (no cudaMalloc allowed)
__device__ float g_logits[(size_t)NN * TOT];   // [n][token], 52.4 MB
__device__ float g_lse[TOT];                   // per-token logsumexp
__device__ float g_msum[BB * NN];              // per-(b,n) logit sums
__device__ int   g_maxid[BB];
__device__ int   g_cand[BB * NCAND];           // candidate token indices
__device__ float g_cscore[BB * NCAND];         // exact scores of candidates
__device__ int   g_topk[BB * KSEL];
__device__ __align__(16) uint32_t g_wswz[NCH16 * WCH1];

__device__ __forceinline__ uint32_t pack2bf(float a, float b) {
    __nv_bfloat162 p = __float22bfloat162_rn(make_float2(a, b));
    return *reinterpret_cast<uint32_t*>(&p);
}

// ---------------------------------------------------------------------------
// K-1: W -> bf16, fragment-swizzled in global (unchanged, proven).
// ---------------------------------------------------------------------------
__global__ void wconv_kernel(const float* __restrict__ W) {
    int i = blockIdx.x * blockDim.x + threadIdx.x;
    if (i >= NCH16 * WCH1) return;
    int c = i / WCH1;
    int rem = i % WCH1;
    int n = rem >> 3, p = rem & 7;
    float v0 = 0.f, v1 = 0.f;
    if (n < NN) {
        int k = c * 16 + 2 * p;
        v0 = W[(size_t)n * CC + k];
        v1 = W[(size_t)n * CC + k + 1];
    }
    int w = (p & 3) * 2 + (p >> 2);
    g_wswz[c * WCH1 + n * 8 + w] = pack2bf(v0, v1);
}

// ---------------------------------------------------------------------------
// K2: APPROX tensor-core logits GEMM v2.
// Block 128 tokens x 224 classes, 512 thr = 4(M) x 4(N) warps.
// k32 chunks (2 k16 halves, addressing identical per half to proven v1).
// 3-stage cp.async pipeline for W; 2-stage register-staged x (fp32->bf16).
// ---------------------------------------------------------------------------
#define MMA_BF16(d, a, b0_, b1_)                                            \
    asm volatile(                                                           \
        "mma.sync.aligned.m16n8k16.row.col.f32.bf16.bf16.f32 "              \
        "{%0,%1,%2,%3}, {%4,%5,%6,%7}, {%8,%9}, {%0,%1,%2,%3};"             \
        : "+f"(d[0]), "+f"(d[1]), "+f"(d[2]), "+f"(d[3])                    \
        : "r"(a[0]), "r"(a[1]), "r"(a[2]), "r"(a[3]), "r"(b0_), "r"(b1_))

#define XSBUF 2048            // u32 per x stage: [2 half][128][8]
#define WSBUF (2 * WCH1)      // u32 per W stage: [2 half][224][8] = 3584
#define SMEMB ((2 * XSBUF + 3 * WSBUF + NPAD + 2 * 512) * 4)

__global__ __launch_bounds__(512, 1)
void score_mma_kernel(const float* __restrict__ x,
                      const float* __restrict__ bias) {
    extern __shared__ uint32_t sm[];
    uint32_t* xs = sm;                        // [2 buf][2 half][128][8]
    uint32_t* ws = sm + 2 * XSBUF;            // [3 buf][2 half][224][8]
    float* bias_s = (float*)(ws + 3 * WSBUF); // [224]
    float* p_mx = bias_s + NPAD;              // [128][4]
    float* p_se = p_mx + 512;

    int tid  = threadIdx.x;
    int warp = tid >> 5, lane = tid & 31;
    int gid  = lane >> 2, tig = lane & 3;
    int mw   = warp >> 2, nw = warp & 3;
    int token0 = blockIdx.x * 128;            // 16 blocks per batch

    for (int n = tid; n < NPAD; n += 512)
        bias_s[n] = (n < NN) ? __ldg(&bias[n]) : -1e30f;

    float acc[2][7][4];
    #pragma unroll
    for (int mt = 0; mt < 2; mt++)
        #pragma unroll
        for (int nt = 0; nt < 7; nt++)
            #pragma unroll
            for (int r = 0; r < 4; r++) acc[mt][nt][r] = 0.f;

    const float* xbase = x + (size_t)token0 * CC;

    // x staging: 1024 (row, k-pair) tasks over 512 threads, both halves
    int xrow  = tid >> 3;           // rows 0..63
    int xrow2 = xrow + 64;          // rows 64..127 ((tid+512)>>3)
    int xp    = tid & 7;            // same k-pair for both tasks
    int xw    = (xp & 3) * 2 + (xp >> 2);
    float2 rx[2][2];                // [task][half]

    auto ldx = [&](int c) {
        const float* p0 = xbase + (size_t)xrow  * CC + c * 32 + 2 * xp;
        const float* p1 = xbase + (size_t)xrow2 * CC + c * 32 + 2 * xp;
        rx[0][0] = *(const float2*)p0;  rx[0][1] = *(const float2*)(p0 + 16);
        rx[1][0] = *(const float2*)p1;  rx[1][1] = *(const float2*)(p1 + 16);
    };
    auto stx = [&](int xb) {
        uint32_t* base = xs + xb * XSBUF;
        base[0 * 1024 + xrow  * 8 + xw] = pack2bf(rx[0][0].x, rx[0][0].y);
        base[1 * 1024 + xrow  * 8 + xw] = pack2bf(rx[0][1].x, rx[0][1].y);
        base[0 * 1024 + xrow2 * 8 + xw] = pack2bf(rx[1][0].x, rx[1][0].y);
        base[1 * 1024 + xrow2 * 8 + xw] = pack2bf(rx[1][1].x, rx[1][1].y);
    };
    auto cpW = [&](int c, int wb) {
        const uint4* src = (const uint4*)(g_wswz + (size_t)(2 * c) * WCH1);
        uint32_t dst = (uint32_t)__cvta_generic_to_shared(ws + wb * WSBUF);
        asm volatile("cp.async.cg.shared.global [%0], [%1], 16;"
                     :: "r"(dst + tid * 16), "l"(src + tid));
        if (tid < 384)
            asm volatile("cp.async.cg.shared.global [%0], [%1], 16;"
                         :: "r"(dst + (tid + 512) * 16), "l"(src + tid + 512));
    };

    // Prologue: W chunks 0,1 in flight; x chunk 0 in smem, chunk 1 in regs
    cpW(0, 0); asm volatile("cp.async.commit_group;");
    cpW(1, 1); asm volatile("cp.async.commit_group;");
    ldx(0); stx(0);
    ldx(1);
    asm volatile("cp.async.wait_group 1;");
    __syncthreads();

    for (int c = 0; c < NCH32; c++) {
        int xb = c & 1, wb = c % 3;
        const uint32_t* xsb = xs + xb * XSBUF;
        const uint32_t* wsb = ws + wb * WSBUF;

        #pragma unroll
        for (int h = 0; h < 2; h++) {
            uint32_t af[2][4];
            #pragma unroll
            for (int mt = 0; mt < 2; mt++) {
                int row0 = mw * 32 + mt * 16 + gid;
                const uint32_t* pa = xsb + h * 1024 + row0 * 8 + tig * 2;
                uint2 t0 = *(const uint2*)pa;
                uint2 t1 = *(const uint2*)(pa + 64);
                af[mt][0] = t0.x;  af[mt][2] = t0.y;
                af[mt][1] = t1.x;  af[mt][3] = t1.y;
            }
            #pragma unroll
            for (int nt = 0; nt < 7; nt++) {
                int nrow = nw * 56 + nt * 8 + gid;
                uint2 B0 = *(const uint2*)(wsb + h * WCH1 + nrow * 8 + tig * 2);
                MMA_BF16(acc[0][nt], af[0], B0.x, B0.y);
                MMA_BF16(acc[1][nt], af[1], B0.x, B0.y);
            }
        }

        if (c + 1 < NCH32) {
            stx(xb ^ 1);                           // x for chunk c+1
            if (c + 2 < NCH32) { ldx(c + 2); cpW(c + 2, (c + 2) % 3); }
            asm volatile("cp.async.commit_group;");
            asm volatile("cp.async.wait_group 1;");
            __syncthreads();
        }
    }

    // ---- bias add + logit store (transposed [n][token]) + LSE
    #pragma unroll
    for (int nt = 0; nt < 7; nt++) {
        int n0 = nw * 56 + nt * 8 + tig * 2;
        float b0 = bias_s[n0], b1 = bias_s[n0 + 1];
        #pragma unroll
        for (int mt = 0; mt < 2; mt++) {
            acc[mt][nt][0] += b0; acc[mt][nt][1] += b1;
            acc[mt][nt][2] += b0; acc[mt][nt][3] += b1;
        }
        if (n0 < NN) {
            #pragma unroll
            for (int mt = 0; mt < 2; mt++) {
                int r0 = token0 + mw * 32 + mt * 16 + gid;
                g_logits[(size_t)n0 * TOT + r0]           = acc[mt][nt][0];
                g_logits[(size_t)(n0 + 1) * TOT + r0]     = acc[mt][nt][1];
                g_logits[(size_t)n0 * TOT + r0 + 8]       = acc[mt][nt][2];
                g_logits[(size_t)(n0 + 1) * TOT + r0 + 8] = acc[mt][nt][3];
            }
        }
    }

    #pragma unroll
    for (int mt = 0; mt < 2; mt++) {
        #pragma unroll
        for (int half = 0; half < 2; half++) {
            float mx = -1e30f;
            #pragma unroll
            for (int nt = 0; nt < 7; nt++)
                mx = fmaxf(mx, fmaxf(acc[mt][nt][2 * half],
                                     acc[mt][nt][2 * half + 1]));
            mx = fmaxf(mx, __shfl_xor_sync(0xffffffffu, mx, 1));
            mx = fmaxf(mx, __shfl_xor_sync(0xffffffffu, mx, 2));

            float se = 0.f;
            #pragma unroll
            for (int nt = 0; nt < 7; nt++) {
                se += expf(acc[mt][nt][2 * half] - mx)
                    + expf(acc[mt][nt][2 * half + 1] - mx);
            }
            se += __shfl_xor_sync(0xffffffffu, se, 1);
            se += __shfl_xor_sync(0xffffffffu, se, 2);

            if (tig == 0) {
                int row = mw * 32 + mt * 16 + half * 8 + gid;
                p_mx[row * 4 + nw] = mx;
                p_se[row * 4 + nw] = se;
            }
        }
    }
    __syncthreads();

    if (tid < 128) {
        float m0 = p_mx[tid * 4 + 0], m1 = p_mx[tid * 4 + 1];
        float m2 = p_mx[tid * 4 + 2], m3 = p_mx[tid * 4 + 3];
        float M = fmaxf(fmaxf(m0, m1), fmaxf(m2, m3));
        float se = p_se[tid * 4 + 0] * expf(m0 - M)
                 + p_se[tid * 4 + 1] * expf(m1 - M)
                 + p_se[tid * 4 + 2] * expf(m2 - M)
                 + p_se[tid * 4 + 3] * expf(m3 - M);
        g_lse[token0 + tid] = M + logf(se);
    }
}

// ---------------------------------------------------------------------------
// K3a: per-(b,n) sum of logits over tokens.
// ---------------------------------------------------------------------------
__global__ void csum_kernel() {
    __shared__ float red[128];
    int b = blockIdx.x / NN, n = blockIdx.x % NN;
    const float* p = g_logits + (size_t)n * TOT + b * SS;
    float s = 0.f;
    for (int t = threadIdx.x; t < SS; t += 128) s += p[t];
    red[threadIdx.x] = s;
    __syncthreads();
    for (int o = 64; o > 0; o >>= 1) {
        if (threadIdx.x < o) red[threadIdx.x] += red[threadIdx.x + o];
        __syncthreads();
    }
    if (threadIdx.x == 0) g_msum[b * NN + n] = red[0];
}

// ---------------------------------------------------------------------------
// K3b: per-batch argmax over the NN sums.
// ---------------------------------------------------------------------------
__global__ void argmax2_kernel() {
    __shared__ float vals[256];
    __shared__ int   idxs[256];
    int b = blockIdx.x, n = threadIdx.x;
    vals[n] = (n < NN) ? g_msum[b * NN + n] : -INFINITY;
    idxs[n] = (n < NN) ? n : (1 << 30);
    __syncthreads();
    for (int o = 128; o > 0; o >>= 1) {
        if (n < o) {
            float v2 = vals[n + o]; int i2 = idxs[n + o];
            float v1 = vals[n];     int i1 = idxs[n];
            if (v2 > v1 || (v2 == v1 && i2 < i1)) { vals[n] = v2; idxs[n] = i2; }
        }
        __syncthreads();
    }
    if (n == 0) g_maxid[b] = idxs[0];
}

// ---------------------------------------------------------------------------
// K4: per-batch bitonic sort of 2048 approx scores -> top-256 candidates.
// Score computed inline: logit[id] - lse (fill kernel fused away).
// ---------------------------------------------------------------------------
__global__ void cand_kernel() {
    __shared__ float s[SS];
    __shared__ int   si[SS];
    int b = blockIdx.x;
    int id = g_maxid[b];
    const float* lg = g_logits + (size_t)id * TOT + b * SS;
    const float* ls = g_lse + b * SS;
    for (int t = threadIdx.x; t < SS; t += blockDim.x) {
        s[t]  = lg[t] - ls[t];
        si[t] = t;
    }
    __syncthreads();
    for (int k = 2; k <= SS; k <<= 1) {
        for (int j = k >> 1; j > 0; j >>= 1) {
            for (int t = threadIdx.x; t < SS; t += blockDim.x) {
                int ixj = t ^ j;
                if (ixj > t) {
                    float a = s[t],  c = s[ixj];
                    int  ai = si[t], ci = si[ixj];
                    bool aBetter = (a > c) || (a == c && ai < ci);
                    bool descHere = ((t & k) == 0);
                    bool doSwap = descHere ? !aBetter : aBetter;
                    if (doSwap) {
                        s[t] = c;  s[ixj] = a;
                        si[t] = ci; si[ixj] = ai;
                    }
                }
            }
            __syncthreads();
        }
    }
    for (int t = threadIdx.x; t < NCAND; t += blockDim.x)
        g_cand[b * NCAND + t] = si[t];
}

// ---------------------------------------------------------------------------
// K5: EXACT rescore of candidates — verbatim fp32 math (proven rel_err 0.0).
// ---------------------------------------------------------------------------
__global__ __launch_bounds__(256, 2)
void exact_kernel(const float* __restrict__ x,
                  const float* __restrict__ W,
                  const float* __restrict__ bias) {
    __shared__ float x_s[16 * 65];
    __shared__ float w_s[16 * 209];
    __shared__ int   cind[64];

    int tid = threadIdx.x;
    int tx = tid & 15;
    int ty = tid >> 4;
    int b  = blockIdx.x >> 2;
    int c0 = (blockIdx.x & 3) * 64;

    if (tid < 64) cind[tid] = g_cand[b * NCAND + c0 + tid];
    __syncthreads();

    float acc[4][13];
    #pragma unroll
    for (int i = 0; i < 4; i++)
        #pragma unroll
        for (int j = 0; j < 13; j++) acc[i][j] = 0.f;

    const float* xb = x + (size_t)b * SS * CC;

    for (int k0 = 0; k0 < CC; k0 += 16) {
        #pragma unroll
        for (int r = 0; r < 4; r++) {
            int e = tid + r * 256;
            int m = e >> 4, kk = e & 15;
            x_s[kk * 65 + m] = xb[(size_t)cind[m] * CC + k0 + kk];
        }
        #pragma unroll
        for (int r = 0; r < 13; r++) {
            int e = tid + r * 256;
            if (e < 3328) {
                int n = e >> 4, kk = e & 15;
                w_s[kk * 209 + n] =
                    (n < NN) ? __ldg(&W[(size_t)n * CC + k0 + kk]) : 0.f;
            }
        }
        __syncthreads();

        #pragma unroll
        for (int kk = 0; kk < 16; kk++) {
            float xv[4];
            #pragma unroll
            for (int i = 0; i < 4; i++) xv[i] = x_s[kk * 65 + ty * 4 + i];
            #pragma unroll
            for (int j = 0; j < 13; j++) {
                float wv = w_s[kk * 209 + tx + 16 * j];
                #pragma unroll
                for (int i = 0; i < 4; i++)
                    acc[i][j] = fmaf(xv[i], wv, acc[i][j]);
            }
        }
        __syncthreads();
    }

    int id = g_maxid[b];
    #pragma unroll
    for (int i = 0; i < 4; i++) {
        float mx = -1e30f;
        #pragma unroll
        for (int j = 0; j < 13; j++) {
            int n = tx + 16 * j;
            if (n < NN) {
                acc[i][j] += __ldg(&bias[n]);
                mx = fmaxf(mx, acc[i][j]);
            }
        }
        #pragma unroll
        for (int o = 8; o > 0; o >>= 1)
            mx = fmaxf(mx, __shfl_xor_sync(0xffffffffu, mx, o));

        float se = 0.f, lv = 0.f;
        #pragma unroll
        for (int j = 0; j < 13; j++) {
            int n = tx + 16 * j;
            if (n < NN) {
                se += expf(acc[i][j] - mx);
                if (n == id) lv = acc[i][j];
            }
        }
        #pragma unroll
        for (int o = 8; o > 0; o >>= 1) {
            se += __shfl_xor_sync(0xffffffffu, se, o);
            lv += __shfl_xor_sync(0xffffffffu, lv, o);
        }
        if (tx == 0)
            g_cscore[b * NCAND + c0 + ty * 4 + i] = lv - mx - logf(se);
    }
}

// ---------------------------------------------------------------------------
// K6: per-batch sort of 256 candidates by EXACT score (desc, idx asc).
// ---------------------------------------------------------------------------
__global__ void sort2_kernel() {
    __shared__ float s[NCAND];
    __shared__ int   si[NCAND];
    int b = blockIdx.x;
    int t = threadIdx.x;
    s[t]  = g_cscore[b * NCAND + t];
    si[t] = g_cand[b * NCAND + t];
    __syncthreads();
    for (int k = 2; k <= NCAND; k <<= 1) {
        for (int j = k >> 1; j > 0; j >>= 1) {
            int ixj = t ^ j;
            if (ixj > t) {
                float a = s[t],  c = s[ixj];
                int  ai = si[t], ci = si[ixj];
                bool aBetter = (a > c) || (a == c && ai < ci);
                bool descHere = ((t & k) == 0);
                bool doSwap = descHere ? !aBetter : aBetter;
                if (doSwap) {
                    s[t] = c;  s[ixj] = a;
                    si[t] = ci; si[ixj] = ai;
                }
            }
            __syncthreads();
        }
    }
    if (t < KSEL) g_topk[b * KSEL + t] = si[t];
}

// ---------------------------------------------------------------------------
// K7: gather out[b, j, :] = x[b, topk[b][j], :]  (float4 vectorized)
// ---------------------------------------------------------------------------
__global__ void gather_kernel(const float* __restrict__ x,
                              float* __restrict__ out) {
    int row = blockIdx.x;
    int b = row >> 7, j = row & (KSEL - 1);
    int sidx = g_topk[b * KSEL + j];
    const float4* src = (const float4*)(x + ((size_t)b * SS + sidx) * CC);
    float4* dst = (float4*)(out + (size_t)row * CC);
    for (int c = threadIdx.x; c < CC / 4; c += blockDim.x) dst[c] = src[c];
}

// ---------------------------------------------------------------------------
extern "C" void kernel_launch(void* const* d_in, const int* in_sizes, int n_in,
                              void* d_out, int out_size) {
    const float* x    = (const float*)d_in[0];   // [32, 2048, 1536]
    const float* W    = (const float*)d_in[1];   // [200, 1536]
    const float* bias = (const float*)d_in[2];   // [200]
    float* out = (float*)d_out;                  // [32, 128, 1536]

    cudaFuncSetAttribute(score_mma_kernel,
                         cudaFuncAttributeMaxDynamicSharedMemorySize, SMEMB);

    wconv_kernel<<<(NCH16 * WCH1 + 255) / 256, 256>>>(W);
    score_mma_kernel<<<TOT / 128, 512, SMEMB>>>(x, bias);
    csum_kernel<<<BB * NN, 128>>>();
    argmax2_kernel<<<BB, 256>>>();
    cand_kernel<<<BB, 1024>>>();
    exact_kernel<<<(BB * NCAND) / 64, 256>>>(x, W, bias);
    sort2_kernel<<<BB, NCAND>>>();
    gather_kernel<<<BB * KSEL, 256>>>(x, out);
}